// round 1
// baseline (speedup 1.0000x reference)
#include <cuda_runtime.h>
#include <cuda_bf16.h>
#include <cstdint>

// Problem dims (fixed by reference)
#define BATCH   32768
#define NUM_IN  256
#define NUM_HID 512
#define NUM_OUT 64
#define M_NODES (NUM_HID + NUM_OUT)   // 576
#define N_NODES (NUM_IN + M_NODES)    // 832
#define KFAN    32

// Node-major state scratch: state[n][b], n in [0, 832), b in [0, 32768)
__device__ float g_state[(size_t)N_NODES * BATCH];

// ---------------------------------------------------------------------------
// Kernel 1: transpose x [B, 256] -> g_state[0..256)[B]
// ---------------------------------------------------------------------------
__global__ void transpose_x_kernel(const float* __restrict__ x) {
    __shared__ float tile[32][33];
    int bb = blockIdx.x * 32;          // batch tile base
    int nn = blockIdx.y * 32;          // input-node tile base
    int tx = threadIdx.x;              // 0..31
    int ty = threadIdx.y;              // 0..7

    #pragma unroll
    for (int r = 0; r < 32; r += 8) {
        // read x[b][n]: coalesced in n
        tile[ty + r][tx] = x[(size_t)(bb + ty + r) * NUM_IN + (nn + tx)];
    }
    __syncthreads();
    #pragma unroll
    for (int r = 0; r < 32; r += 8) {
        // write state[n][b]: coalesced in b
        g_state[(size_t)(nn + ty + r) * BATCH + (bb + tx)] = tile[tx][ty + r];
    }
}

// ---------------------------------------------------------------------------
// Kernel 2: main sequential DAG evaluation.
// Each thread owns 2 batch columns (float2). No synchronization needed:
// a thread only ever reads state it (or the transpose kernel) wrote in its
// own columns.
// ---------------------------------------------------------------------------
__global__ __launch_bounds__(64, 1)
void neat_main_kernel(const float* __restrict__ w,
                      const float* __restrict__ bias,
                      const int*   __restrict__ src) {
    const int tid = blockIdx.x * 64 + threadIdx.x;   // 0 .. 16383
    const int col = tid * 2;                         // batch column base

    for (int t = 0; t < M_NODES; t++) {
        const int4*   s4 = (const int4*)(src + t * KFAN);
        const float4* w4 = (const float4*)(w + t * KFAN);

        // 4 partial accumulators per batch element for ILP
        float a0 = 0.f, a1 = 0.f, a2 = 0.f, a3 = 0.f;   // elem 0
        float c0 = 0.f, c1 = 0.f, c2 = 0.f, c3 = 0.f;   // elem 1

        #pragma unroll
        for (int q = 0; q < 8; q++) {
            int4   s  = __ldg(&s4[q]);
            float4 ww = __ldg(&w4[q]);
            float2 v0 = *(const float2*)&g_state[(size_t)s.x * BATCH + col];
            float2 v1 = *(const float2*)&g_state[(size_t)s.y * BATCH + col];
            float2 v2 = *(const float2*)&g_state[(size_t)s.z * BATCH + col];
            float2 v3 = *(const float2*)&g_state[(size_t)s.w * BATCH + col];
            a0 = fmaf(v0.x, ww.x, a0);
            a1 = fmaf(v1.x, ww.y, a1);
            a2 = fmaf(v2.x, ww.z, a2);
            a3 = fmaf(v3.x, ww.w, a3);
            c0 = fmaf(v0.y, ww.x, c0);
            c1 = fmaf(v1.y, ww.y, c1);
            c2 = fmaf(v2.y, ww.z, c2);
            c3 = fmaf(v3.y, ww.w, c3);
        }

        float bt = __ldg(&bias[t]);
        float z0 = (a0 + a1) + (a2 + a3) + bt;
        float z1 = (c0 + c1) + (c2 + c3) + bt;
        float o0 = 1.0f / (1.0f + __expf(-z0));
        float o1 = 1.0f / (1.0f + __expf(-z1));

        *(float2*)&g_state[(size_t)(NUM_IN + t) * BATCH + col] = make_float2(o0, o1);
    }
}

// ---------------------------------------------------------------------------
// Kernel 3: gather outputs. out[b][j] = state[768 + j][b], j in [0, 64)
// ---------------------------------------------------------------------------
__global__ void gather_out_kernel(float* __restrict__ out) {
    __shared__ float tile[32][33];
    int bb = blockIdx.x * 32;          // batch tile base
    int jj = blockIdx.y * 32;          // output-node tile base
    int tx = threadIdx.x;
    int ty = threadIdx.y;

    #pragma unroll
    for (int r = 0; r < 32; r += 8) {
        // read state[768 + j][b]: coalesced in b
        tile[ty + r][tx] =
            g_state[(size_t)(NUM_IN + NUM_HID + jj + ty + r) * BATCH + (bb + tx)];
    }
    __syncthreads();
    #pragma unroll
    for (int r = 0; r < 32; r += 8) {
        // write out[b][j]: coalesced in j
        out[(size_t)(bb + ty + r) * NUM_OUT + (jj + tx)] = tile[tx][ty + r];
    }
}

// ---------------------------------------------------------------------------
// Launch
// Input order (metadata): 0 = x [B,256] f32, 1 = w [576,32] f32,
//                         2 = b [576] f32,   3 = edge_src [576,32] i32
// ---------------------------------------------------------------------------
extern "C" void kernel_launch(void* const* d_in, const int* in_sizes, int n_in,
                              void* d_out, int out_size) {
    const float* x    = (const float*)d_in[0];
    const float* w    = (const float*)d_in[1];
    const float* bias = (const float*)d_in[2];
    const int*   src  = (const int*)d_in[3];
    float* out = (float*)d_out;

    (void)in_sizes; (void)n_in; (void)out_size;

    // 1. transpose x into node-major state
    {
        dim3 grid(BATCH / 32, NUM_IN / 32);
        dim3 block(32, 8);
        transpose_x_kernel<<<grid, block>>>(x);
    }
    // 2. sequential DAG evaluation (256 blocks x 64 threads, 2 batch cols/thread)
    {
        neat_main_kernel<<<(BATCH / 2) / 64, 64>>>(w, bias, src);
    }
    // 3. gather outputs
    {
        dim3 grid(BATCH / 32, NUM_OUT / 32);
        dim3 block(32, 8);
        gather_out_kernel<<<grid, block>>>(out);
    }
}

// round 2
// speedup vs baseline: 1.6137x; 1.6137x over previous
#include <cuda_runtime.h>
#include <cstdint>

#define BATCH   32768
#define NUM_IN  256
#define NUM_HID 512
#define NUM_OUT 64
#define M_NODES 576              // non-input nodes
#define N_NODES 832              // total nodes
#define KFAN    32
#define COLS    64               // batch columns per block
#define THREADS 128              // 4 warps
#define ROUNDS  (M_NODES / 2)    // 288 node-pairs
#define CHUNK_NODES 16
#define NCHUNKS (M_NODES / CHUNK_NODES)   // 36

// shared memory word layout
#define ST_WORDS    (N_NODES * COLS)     // 53248 words: state[node][col]
#define PBUF_WORDS  1040                 // 512 src + 512 w + 16 bias (per buffer)
#define STAGE_WORDS 2112                 // max(2*PBUF_WORDS, 64*33 x-staging)
#define FLAG_WORDS  ROUNDS               // 288
#define TOTAL_WORDS (ST_WORDS + STAGE_WORDS + FLAG_WORDS)   // 55648 -> 222592 B

__device__ int g_flags[ROUNDS];

// ---------------------------------------------------------------------------
// Prep: does node (2r+1) read node (2r)?  (node id of target t is NUM_IN + t)
// ---------------------------------------------------------------------------
__global__ void pair_flags_kernel(const int* __restrict__ src) {
    int r = blockIdx.x * blockDim.x + threadIdx.x;
    if (r >= ROUNDS) return;
    int t1 = 2 * r + 1;
    int target = NUM_IN + 2 * r;
    int dep = 0;
    #pragma unroll 8
    for (int k = 0; k < KFAN; k++)
        dep |= (src[t1 * KFAN + k] == target);
    g_flags[r] = dep;
}

// ---------------------------------------------------------------------------
// Fused main kernel: 512 blocks x 128 threads, 64 batch cols per block,
// full node state resident in SMEM.
// ---------------------------------------------------------------------------
extern __shared__ float smem_f[];

__global__ __launch_bounds__(THREADS, 1)
void neat_smem_kernel(const float* __restrict__ x,
                      const float* __restrict__ w,
                      const float* __restrict__ bias,
                      const int*   __restrict__ src,
                      float* __restrict__ out) {
    float* st      = smem_f;                       // [N_NODES][COLS]
    float* stage   = smem_f + ST_WORDS;            // param double-buffer / x staging
    int*   stage_i = (int*)stage;
    int*   sflags  = (int*)(smem_f + ST_WORDS + STAGE_WORDS);

    const int tid  = threadIdx.x;
    const int wid  = tid >> 5;
    const int lane = tid & 31;
    const int b0   = blockIdx.x * COLS;

    // ---- load pair flags into smem ----
    for (int i = tid; i < ROUNDS; i += THREADS) sflags[i] = g_flags[i];

    // ---- input: x[b][n] -> st[n][col], 8 chunks of 32 input nodes ----
    {
        const int half = tid >> 6;         // 0/1
        const int c    = tid & 63;
        for (int ch = 0; ch < 8; ch++) {
            const int nc0 = ch * 32;
            __syncthreads();               // protect staging tile
            #pragma unroll
            for (int i = 0; i < 16; i++) {
                int row = wid * 16 + i;    // batch row within block
                stage[row * 33 + lane] =
                    x[(size_t)(b0 + row) * NUM_IN + nc0 + lane];   // coalesced
            }
            __syncthreads();
            #pragma unroll
            for (int i = 0; i < 16; i++) {
                int nn = half * 16 + i;
                st[(nc0 + nn) * COLS + c] = stage[c * 33 + nn];    // bank-safe
            }
        }
    }
    __syncthreads();

    // ---- param prefetch helper (chunk of 16 nodes into buffer pb) ----
    auto prefetch = [&](int ch, int pb) {
        int*   dS = stage_i + pb * PBUF_WORDS;
        float* dW = stage   + pb * PBUF_WORDS + 512;
        ((int4*)dS)[tid]   = ((const int4*)(src + ch * 512))[tid];          // 512 ints
        ((float4*)dW)[tid] = ((const float4*)(w + ch * 512))[tid];          // 512 floats
        if (tid < CHUNK_NODES)
            stage[pb * PBUF_WORDS + 1024 + tid] = bias[ch * CHUNK_NODES + tid];
    };

    prefetch(0, 0);
    __syncthreads();

    const int p   = wid >> 1;                 // which node of the pair
    const int col = (wid & 1) * 32 + lane;    // this thread's batch column

    // ---- node evaluator ----
    auto do_node = [&](int t, int pb) {
        const int   ln = t & (CHUNK_NODES - 1);
        const int*   ps = stage_i + pb * PBUF_WORDS + ln * KFAN;
        const float* pw = stage   + pb * PBUF_WORDS + 512 + ln * KFAN;
        float a0 = 0.f, a1 = 0.f, a2 = 0.f, a3 = 0.f;
        #pragma unroll
        for (int q = 0; q < 8; q++) {
            int4   s  = *(const int4*)(ps + q * 4);
            float4 ww = *(const float4*)(pw + q * 4);
            a0 = fmaf(st[s.x * COLS + col], ww.x, a0);
            a1 = fmaf(st[s.y * COLS + col], ww.y, a1);
            a2 = fmaf(st[s.z * COLS + col], ww.z, a2);
            a3 = fmaf(st[s.w * COLS + col], ww.w, a3);
        }
        float z = (a0 + a1) + (a2 + a3) + stage[pb * PBUF_WORDS + 1024 + ln];
        float o = __fdividef(1.0f, 1.0f + __expf(-z));
        st[(NUM_IN + t) * COLS + col] = o;
    };

    // ---- main sequential loop: 288 rounds of 2 nodes ----
    for (int r = 0; r < ROUNDS; r++) {
        const int ch = r >> 3;                // 8 rounds per 16-node chunk
        const int pb = ch & 1;
        if ((r & 7) == 0 && (ch + 1) < NCHUNKS)
            prefetch(ch + 1, pb ^ 1);

        const int t   = 2 * r + p;
        const int dep = sflags[r];

        if (!dep) {
            do_node(t, pb);
        } else {
            if (p == 0) do_node(t, pb);
            __syncthreads();
            if (p == 1) do_node(t, pb);
        }
        __syncthreads();
    }

    // ---- output: out[b][j] = st[768 + j][col] ----
    {
        const int c  = tid & 63;
        const int jh = tid >> 6;              // 0/1
        #pragma unroll
        for (int i = 0; i < 8; i++) {
            int j4 = (jh * 8 + i) * 4;        // output group of 4
            float4 v;
            v.x = st[(NUM_IN + NUM_HID + j4 + 0) * COLS + c];
            v.y = st[(NUM_IN + NUM_HID + j4 + 1) * COLS + c];
            v.z = st[(NUM_IN + NUM_HID + j4 + 2) * COLS + c];
            v.w = st[(NUM_IN + NUM_HID + j4 + 3) * COLS + c];
            *(float4*)&out[(size_t)(b0 + c) * NUM_OUT + j4] = v;
        }
    }
}

// ---------------------------------------------------------------------------
extern "C" void kernel_launch(void* const* d_in, const int* in_sizes, int n_in,
                              void* d_out, int out_size) {
    const float* x    = (const float*)d_in[0];
    const float* w    = (const float*)d_in[1];
    const float* bias = (const float*)d_in[2];
    const int*   src  = (const int*)d_in[3];
    float* out = (float*)d_out;
    (void)in_sizes; (void)n_in; (void)out_size;

    cudaFuncSetAttribute(neat_smem_kernel,
                         cudaFuncAttributeMaxDynamicSharedMemorySize,
                         TOTAL_WORDS * 4);

    pair_flags_kernel<<<(ROUNDS + 127) / 128, 128>>>(src);
    neat_smem_kernel<<<BATCH / COLS, THREADS, TOTAL_WORDS * 4>>>(x, w, bias, src, out);
}

// round 3
// speedup vs baseline: 1.8420x; 1.1415x over previous
#include <cuda_runtime.h>
#include <cstdint>

#define BATCH   32768
#define NUM_IN  256
#define NUM_HID 512
#define NUM_OUT 64
#define M_NODES 576
#define N_NODES 832
#define KFAN    32
#define COLS    64
#define THREADS 256
#define SLOTS   8                      // nodes per round
#define RSTRIDE 416                    // words per round in param blob (1664 B = 104 x 16B)
#define RMAX    576                    // worst-case rounds

// round-major param blob: per round r at r*RSTRIDE:
//   [0..128)   src16: slot*16 + j  (two u16 node ids per word)
//   [128..384) w:     128 + slot*32 + k
//   [384..392) bias per slot
//   [392..400) target st-row per slot (int), 832 = dummy
__device__ float g_blob[RMAX * RSTRIDE];
__device__ int   g_sched[RMAX * SLOTS];
__device__ int   g_nrounds;

// ---------------------------------------------------------------------------
// Prep: ASAP levels -> round schedule -> param blob. One block, 576 threads.
// ---------------------------------------------------------------------------
__global__ __launch_bounds__(M_NODES)
void schedule_kernel(const int* __restrict__ src,
                     const float* __restrict__ w,
                     const float* __restrict__ bias) {
    __shared__ unsigned short plist[M_NODES * KFAN];   // non-input preds (t-index)
    __shared__ int lev[M_NODES];
    __shared__ int cnt[M_NODES + 1];
    __shared__ int rbase[M_NODES + 1];
    __shared__ int pos[M_NODES + 1];
    __shared__ int changed, R_sh, lmax_sh;

    const int t = threadIdx.x;   // 0..575, one node per thread

    // compact non-input predecessors
    int np = 0;
    for (int k = 0; k < KFAN; k++) {
        int s = src[t * KFAN + k];
        if (s >= NUM_IN) plist[t * KFAN + np++] = (unsigned short)(s - NUM_IN);
    }
    lev[t] = 0;
    __syncthreads();

    // chunked Gauss-Seidel to fixpoint (preds are always lower-indexed)
    for (int c = 0; c < M_NODES / 64; c++) {
        const int lo = c * 64, hi = lo + 64;
        const bool mine = (t >= lo && t < hi);
        while (true) {
            if (t == 0) changed = 0;
            __syncthreads();
            if (mine) {
                int m = 0;
                for (int j = 0; j < np; j++) {
                    int p = plist[t * KFAN + j];
                    int l = lev[p];
                    m = (l > m) ? l : m;
                }
                if (m + 1 != lev[t]) { lev[t] = m + 1; changed = 1; }
            }
            __syncthreads();
            if (!changed) break;
        }
    }

    // histogram over levels
    for (int i = t; i <= M_NODES; i += M_NODES) { cnt[i] = 0; pos[i] = 0; }
    if (t == 0) lmax_sh = 0;
    __syncthreads();
    atomicAdd(&cnt[lev[t]], 1);
    atomicMax(&lmax_sh, lev[t]);
    __syncthreads();

    if (t == 0) {
        int r = 0;
        for (int L = 1; L <= lmax_sh; L++) { rbase[L] = r; r += (cnt[L] + SLOTS - 1) >> 3; }
        R_sh = r;
        g_nrounds = r;
    }
    __syncthreads();
    const int R = R_sh;

    for (int i = t; i < R * SLOTS; i += M_NODES) g_sched[i] = -1;
    __syncthreads();

    // slot assignment (any order within a level is valid)
    {
        int L = lev[t];
        int p = atomicAdd(&pos[L], 1);
        g_sched[(rbase[L] + (p >> 3)) * SLOTS + (p & 7)] = t;
    }
    __syncthreads();

    // fill blob: src16
    for (int u = t; u < R * SLOTS * 16; u += M_NODES) {
        int slot = u >> 4, j = u & 15;
        int nd = g_sched[slot];
        unsigned v = 0;
        if (nd >= 0) {
            unsigned a = (unsigned)src[nd * KFAN + 2 * j];
            unsigned b = (unsigned)src[nd * KFAN + 2 * j + 1];
            v = (a & 0xFFFFu) | (b << 16);
        }
        int rr = slot >> 3, ss = slot & 7;
        ((unsigned*)g_blob)[rr * RSTRIDE + ss * 16 + j] = v;
    }
    // w
    for (int u = t; u < R * SLOTS * KFAN; u += M_NODES) {
        int slot = u >> 5, k = u & 31;
        int nd = g_sched[slot];
        float v = (nd >= 0) ? w[nd * KFAN + k] : 0.0f;
        int rr = slot >> 3, ss = slot & 7;
        g_blob[rr * RSTRIDE + 128 + ss * 32 + k] = v;
    }
    // bias + target
    for (int u = t; u < R * SLOTS; u += M_NODES) {
        int nd = g_sched[u];
        int rr = u >> 3, ss = u & 7;
        g_blob[rr * RSTRIDE + 384 + ss] = (nd >= 0) ? bias[nd] : 0.0f;
        ((int*)g_blob)[rr * RSTRIDE + 392 + ss] = (nd >= 0) ? (NUM_IN + nd) : N_NODES;
    }
}

// ---------------------------------------------------------------------------
// Main kernel: 512 blocks x 256 threads, 64 batch columns per block,
// full state in SMEM, 8 independent nodes per round, 1 barrier per round.
// ---------------------------------------------------------------------------
#define ST_WORDS    ((N_NODES + 1) * COLS)   // 53312 (incl. dummy row 832)
#define STAGE_WORDS 1088                     // 64x17 input staging >= 2*RSTRIDE? no:
// pbuf double buffer = 2*416 = 832 words; staging needs 1088 (input) / 1040 (output)
#define TOTAL_WORDS (ST_WORDS + STAGE_WORDS)

extern __shared__ float smem_f[];

__device__ __forceinline__ void cp16(void* sdst, const void* gsrc) {
    uint32_t s = (uint32_t)__cvta_generic_to_shared(sdst);
    asm volatile("cp.async.cg.shared.global [%0], [%1], 16;\n" :: "r"(s), "l"(gsrc));
}

__global__ __launch_bounds__(THREADS, 1)
void neat_level_kernel(const float* __restrict__ x,
                       float* __restrict__ out) {
    float* st    = smem_f;                 // [(N_NODES+1)][COLS]
    float* stage = smem_f + ST_WORDS;      // param double buffer / transpose staging

    const int tid  = threadIdx.x;
    const int wid  = tid >> 5;
    const int lane = tid & 31;
    const int b0   = blockIdx.x * COLS;
    const int R    = g_nrounds;

    // ---- input transpose: x[b][n] -> st[n][col], 16 chunks of 16 inputs ----
    for (int ch = 0; ch < 16; ch++) {
        const int nc0 = ch * 16;
        __syncthreads();
        #pragma unroll
        for (int pass = 0; pass < 4; pass++) {
            int rr = pass * 16 + (tid >> 4);
            int c  = tid & 15;
            stage[rr * 17 + c] = x[(size_t)(b0 + rr) * NUM_IN + nc0 + c];
        }
        __syncthreads();
        #pragma unroll
        for (int pass = 0; pass < 4; pass++) {
            int cc  = pass * 4 + (tid >> 6);
            int col = tid & 63;
            st[(nc0 + cc) * COLS + col] = stage[col * 17 + cc];
        }
    }
    __syncthreads();

    // ---- prefetch round 0 params ----
    if (tid < RSTRIDE / 4) cp16(stage + tid * 4, g_blob + tid * 4);
    asm volatile("cp.async.commit_group;\n");
    asm volatile("cp.async.wait_group 0;\n" ::: "memory");
    __syncthreads();

    float* stcol = st + lane * 2;

    // ---- main rounds ----
    for (int r = 0; r < R; r++) {
        float* P  = stage + (r & 1) * RSTRIDE;
        float* Pn = stage + ((r + 1) & 1) * RSTRIDE;
        if (r + 1 < R && tid < RSTRIDE / 4)
            cp16(Pn + tid * 4, g_blob + (size_t)(r + 1) * RSTRIDE + tid * 4);
        asm volatile("cp.async.commit_group;\n");

        // this warp's node
        const unsigned* s16 = (const unsigned*)P + wid * 16;
        const float*    ww  = P + 128 + wid * 32;
        const float     bt  = P[384 + wid];
        const int       tgt = ((const int*)P)[392 + wid];

        float ax = 0.f, ay = 0.f, bx2 = 0.f, by2 = 0.f;
        float cx = 0.f, cy = 0.f, dx2 = 0.f, dy2 = 0.f;
        #pragma unroll
        for (int q = 0; q < 8; q++) {
            unsigned u0 = s16[2 * q], u1 = s16[2 * q + 1];
            float4 w4 = *(const float4*)(ww + 4 * q);
            float2 v0 = *(const float2*)(stcol + ((u0 & 0xFFFFu) << 6));
            float2 v1 = *(const float2*)(stcol + ((u0 >> 16) << 6));
            float2 v2 = *(const float2*)(stcol + ((u1 & 0xFFFFu) << 6));
            float2 v3 = *(const float2*)(stcol + ((u1 >> 16) << 6));
            ax  = fmaf(v0.x, w4.x, ax);  ay  = fmaf(v0.y, w4.x, ay);
            bx2 = fmaf(v1.x, w4.y, bx2); by2 = fmaf(v1.y, w4.y, by2);
            cx  = fmaf(v2.x, w4.z, cx);  cy  = fmaf(v2.y, w4.z, cy);
            dx2 = fmaf(v3.x, w4.w, dx2); dy2 = fmaf(v3.y, w4.w, dy2);
        }
        float z0 = (ax + bx2) + (cx + dx2) + bt;
        float z1 = (ay + by2) + (cy + dy2) + bt;
        float o0 = __fdividef(1.0f, 1.0f + __expf(-z0));
        float o1 = __fdividef(1.0f, 1.0f + __expf(-z1));
        *(float2*)(stcol + (tgt << 6)) = make_float2(o0, o1);

        asm volatile("cp.async.wait_group 0;\n" ::: "memory");
        __syncthreads();
    }

    // ---- output: out[b][j] = st[768+j][col], 4 chunks of 16 outputs ----
    for (int ch = 0; ch < 4; ch++) {
        const int j0 = ch * 16;
        __syncthreads();
        #pragma unroll
        for (int pass = 0; pass < 4; pass++) {
            int j   = pass * 4 + (tid >> 6);
            int col = tid & 63;
            stage[j * 65 + col] = st[(NUM_IN + NUM_HID + j0 + j) * COLS + col];
        }
        __syncthreads();
        #pragma unroll
        for (int pass = 0; pass < 4; pass++) {
            int rr = pass * 16 + (tid >> 4);
            int j  = tid & 15;
            out[(size_t)(b0 + rr) * NUM_OUT + j0 + j] = stage[j * 65 + rr];
        }
    }
}

// ---------------------------------------------------------------------------
extern "C" void kernel_launch(void* const* d_in, const int* in_sizes, int n_in,
                              void* d_out, int out_size) {
    const float* x    = (const float*)d_in[0];
    const float* w    = (const float*)d_in[1];
    const float* bias = (const float*)d_in[2];
    const int*   src  = (const int*)d_in[3];
    float* out = (float*)d_out;
    (void)in_sizes; (void)n_in; (void)out_size;

    cudaFuncSetAttribute(neat_level_kernel,
                         cudaFuncAttributeMaxDynamicSharedMemorySize,
                         TOTAL_WORDS * 4);

    schedule_kernel<<<1, M_NODES>>>(src, w, bias);
    neat_level_kernel<<<BATCH / COLS, THREADS, TOTAL_WORDS * 4>>>(x, out);
}

// round 4
// speedup vs baseline: 2.0020x; 1.0869x over previous
#include <cuda_runtime.h>
#include <cstdint>

#define BATCH   32768
#define NUM_IN  256
#define NUM_HID 512
#define NUM_OUT 64
#define M_NODES 576
#define N_NODES 832
#define KFAN    32
#define COLS    64
#define THREADS 512            // 16 warps
#define SLOTS   16             // nodes per round
#define RSTRIDE 800            // words per round: 256 src16 + 512 w + 16 bias + 16 tgt
#define RMAX    576

// round-major param blob, per round r at r*RSTRIDE:
//   [0..256)    src16  (slot*16 + j): two u16 node ids per word
//   [256..768)  w      (256 + slot*32 + k)
//   [768..784)  bias per slot
//   [784..800)  target st-row per slot (int), N_NODES = dummy
__device__ float g_blob[(size_t)RMAX * RSTRIDE];
__device__ int   g_sched[RMAX * SLOTS];
__device__ int   g_nrounds;

// ---------------------------------------------------------------------------
// Kernel A: greedy list scheduling. 1 block, 576 threads (one per node).
// Round r takes up to SLOTS nodes whose preds are all scheduled in rounds < r.
// ---------------------------------------------------------------------------
__global__ __launch_bounds__(M_NODES)
void schedule_kernel(const int* __restrict__ src) {
    __shared__ unsigned short plist[M_NODES * KFAN];
    __shared__ short npred[M_NODES];
    __shared__ int   rnd[M_NODES];
    __shared__ int   picked, remaining;

    const int t = threadIdx.x;

    int np = 0;
    #pragma unroll 4
    for (int k = 0; k < KFAN; k++) {
        int s = src[t * KFAN + k];
        if (s >= NUM_IN) plist[t * KFAN + np++] = (unsigned short)(s - NUM_IN);
    }
    npred[t] = (short)np;
    rnd[t] = -1;
    for (int i = t; i < RMAX * SLOTS; i += M_NODES) g_sched[i] = -1;
    if (t == 0) remaining = M_NODES;
    __syncthreads();

    int r = 0;
    while (remaining > 0 && r < RMAX) {
        bool ready = false;
        if (rnd[t] < 0) {
            ready = true;
            const int n = npred[t];
            for (int j = 0; j < n; j++)
                if (rnd[plist[t * KFAN + j]] < 0) { ready = false; break; }
        }
        if (t == 0) picked = 0;
        __syncthreads();                       // ready reads done before writes
        if (ready) {
            int p = atomicAdd(&picked, 1);
            if (p < SLOTS) {
                rnd[t] = r;
                g_sched[r * SLOTS + p] = t;
                atomicSub(&remaining, 1);
            }
        }
        __syncthreads();
        r++;
    }
    if (t == 0) g_nrounds = r;
}

// ---------------------------------------------------------------------------
// Kernel B: grid-parallel blob fill. One block per round (fills all RMAX
// rounds deterministically; unscheduled slots are dummies).
// ---------------------------------------------------------------------------
__global__ __launch_bounds__(256)
void blob_fill_kernel(const int* __restrict__ src,
                      const float* __restrict__ w,
                      const float* __restrict__ bias) {
    const int r = blockIdx.x;
    float* Pr = g_blob + (size_t)r * RSTRIDE;
    const int tid = threadIdx.x;

    // src16: 256 words, one per thread
    {
        int slot = tid >> 4, j = tid & 15;
        int nd = g_sched[r * SLOTS + slot];
        unsigned v = 0;
        if (nd >= 0) {
            unsigned a = (unsigned)src[nd * KFAN + 2 * j];
            unsigned b = (unsigned)src[nd * KFAN + 2 * j + 1];
            v = (a & 0xFFFFu) | (b << 16);
        }
        ((unsigned*)Pr)[slot * 16 + j] = v;
    }
    // w: 512 words, two per thread
    #pragma unroll
    for (int u = 0; u < 2; u++) {
        int q = tid + u * 256;
        int slot = q >> 5, k = q & 31;
        int nd = g_sched[r * SLOTS + slot];
        Pr[256 + slot * 32 + k] = (nd >= 0) ? w[nd * KFAN + k] : 0.0f;
    }
    // bias + target
    if (tid < SLOTS) {
        int nd = g_sched[r * SLOTS + tid];
        Pr[768 + tid] = (nd >= 0) ? bias[nd] : 0.0f;
        ((int*)Pr)[784 + tid] = (nd >= 0) ? (NUM_IN + nd) : N_NODES;
    }
}

// ---------------------------------------------------------------------------
// Main kernel: 512 blocks x 512 threads, 64 batch columns per block,
// full state in SMEM, 16 independent nodes per round (1 warp per node),
// dummy slots skipped, 1 barrier per round.
// ---------------------------------------------------------------------------
#define ST_WORDS    ((N_NODES + 1) * COLS)         // 53312
#define STAGE_WORDS 2112                            // max(64x33 staging, 2*RSTRIDE=1600)
#define TOTAL_WORDS (ST_WORDS + STAGE_WORDS)       // 55424 -> 221696 B

extern __shared__ float smem_f[];

__device__ __forceinline__ void cp16(void* sdst, const void* gsrc) {
    uint32_t s = (uint32_t)__cvta_generic_to_shared(sdst);
    asm volatile("cp.async.cg.shared.global [%0], [%1], 16;\n" :: "r"(s), "l"(gsrc));
}

__global__ __launch_bounds__(THREADS, 1)
void neat_level_kernel(const float* __restrict__ x,
                       float* __restrict__ out) {
    float* st    = smem_f;                 // [(N_NODES+1)][COLS]
    float* stage = smem_f + ST_WORDS;      // param double buffer / transpose staging

    const int tid  = threadIdx.x;
    const int wid  = tid >> 5;
    const int lane = tid & 31;
    const int b0   = blockIdx.x * COLS;
    const int R    = g_nrounds;

    // ---- input transpose: x[b][n] -> st[n][col], 8 chunks of 32 inputs ----
    for (int ch = 0; ch < 8; ch++) {
        const int nc0 = ch * 32;
        __syncthreads();
        #pragma unroll
        for (int i = 0; i < 4; i++) {
            int idx = tid + i * THREADS;
            int row = idx >> 5, c = idx & 31;
            stage[row * 33 + c] = x[(size_t)(b0 + row) * NUM_IN + nc0 + c];
        }
        __syncthreads();
        #pragma unroll
        for (int i = 0; i < 4; i++) {
            int idx = tid + i * THREADS;
            int n = idx >> 6, col = idx & 63;
            st[(nc0 + n) * COLS + col] = stage[col * 33 + n];
        }
    }
    __syncthreads();

    // ---- prefetch round 0 params ----
    if (tid < RSTRIDE / 4) cp16(stage + tid * 4, g_blob + tid * 4);
    asm volatile("cp.async.commit_group;\n");
    asm volatile("cp.async.wait_group 0;\n" ::: "memory");
    __syncthreads();

    float* stcol = st + lane * 2;

    // ---- main rounds: warp wid evaluates slot wid over all 64 columns ----
    for (int r = 0; r < R; r++) {
        float* P  = stage + (r & 1) * RSTRIDE;
        float* Pn = stage + ((r + 1) & 1) * RSTRIDE;
        if (r + 1 < R && tid < RSTRIDE / 4)
            cp16(Pn + tid * 4, g_blob + (size_t)(r + 1) * RSTRIDE + tid * 4);
        asm volatile("cp.async.commit_group;\n");

        const int tgt = ((const int*)P)[784 + wid];
        if (tgt < N_NODES) {                       // skip dummy slots entirely
            const unsigned* s16 = (const unsigned*)P + wid * 16;
            const float*    ww  = P + 256 + wid * 32;
            const float     bt  = P[768 + wid];

            float ax = 0.f, ay = 0.f, bx2 = 0.f, by2 = 0.f;
            float cx = 0.f, cy = 0.f, dx2 = 0.f, dy2 = 0.f;
            #pragma unroll
            for (int q = 0; q < 8; q++) {
                unsigned u0 = s16[2 * q], u1 = s16[2 * q + 1];
                float4 w4 = *(const float4*)(ww + 4 * q);
                float2 v0 = *(const float2*)(stcol + ((u0 & 0xFFFFu) << 6));
                float2 v1 = *(const float2*)(stcol + ((u0 >> 16) << 6));
                float2 v2 = *(const float2*)(stcol + ((u1 & 0xFFFFu) << 6));
                float2 v3 = *(const float2*)(stcol + ((u1 >> 16) << 6));
                ax  = fmaf(v0.x, w4.x, ax);  ay  = fmaf(v0.y, w4.x, ay);
                bx2 = fmaf(v1.x, w4.y, bx2); by2 = fmaf(v1.y, w4.y, by2);
                cx  = fmaf(v2.x, w4.z, cx);  cy  = fmaf(v2.y, w4.z, cy);
                dx2 = fmaf(v3.x, w4.w, dx2); dy2 = fmaf(v3.y, w4.w, dy2);
            }
            float z0 = (ax + bx2) + (cx + dx2) + bt;
            float z1 = (ay + by2) + (cy + dy2) + bt;
            float o0 = __fdividef(1.0f, 1.0f + __expf(-z0));
            float o1 = __fdividef(1.0f, 1.0f + __expf(-z1));
            *(float2*)(stcol + (tgt << 6)) = make_float2(o0, o1);
        }

        asm volatile("cp.async.wait_group 0;\n" ::: "memory");
        __syncthreads();
    }

    // ---- output: out[b][j] = st[768+j][col], 2 chunks of 32 outputs ----
    for (int ch = 0; ch < 2; ch++) {
        const int j0 = ch * 32;
        __syncthreads();
        #pragma unroll
        for (int i = 0; i < 4; i++) {
            int idx = tid + i * THREADS;
            int jj = idx >> 6, col = idx & 63;
            stage[col * 33 + jj] = st[(NUM_IN + NUM_HID + j0 + jj) * COLS + col];
        }
        __syncthreads();
        #pragma unroll
        for (int i = 0; i < 4; i++) {
            int idx = tid + i * THREADS;
            int row = idx >> 5, j = idx & 31;
            out[(size_t)(b0 + row) * NUM_OUT + j0 + j] = stage[row * 33 + j];
        }
    }
}

// ---------------------------------------------------------------------------
extern "C" void kernel_launch(void* const* d_in, const int* in_sizes, int n_in,
                              void* d_out, int out_size) {
    const float* x    = (const float*)d_in[0];
    const float* w    = (const float*)d_in[1];
    const float* bias = (const float*)d_in[2];
    const int*   src  = (const int*)d_in[3];
    float* out = (float*)d_out;
    (void)in_sizes; (void)n_in; (void)out_size;

    cudaFuncSetAttribute(neat_level_kernel,
                         cudaFuncAttributeMaxDynamicSharedMemorySize,
                         TOTAL_WORDS * 4);

    schedule_kernel<<<1, M_NODES>>>(src);
    blob_fill_kernel<<<RMAX, 256>>>(src, w, bias);
    neat_level_kernel<<<BATCH / COLS, THREADS, TOTAL_WORDS * 4>>>(x, out);
}